// round 11
// baseline (speedup 1.0000x reference)
#include <cuda_runtime.h>

#define KS 7
#define TILE_W 128
#define TILE_H 64

typedef unsigned long long u64;

__device__ __forceinline__ u64 pk2(float lo, float hi) {
    u64 r; asm("mov.b64 %0, {%1,%2};" : "=l"(r) : "f"(lo), "f"(hi)); return r;
}
__device__ __forceinline__ void fma2(u64& d, u64 a, u64 b) {
    asm("fma.rn.f32x2 %0, %1, %2, %0;" : "+l"(d) : "l"(a), "l"(b));
}
__device__ __forceinline__ void unpk2(u64 v, float& lo, float& hi) {
    asm("mov.b64 {%0,%1}, %2;" : "=f"(lo), "=f"(hi) : "l"(v));
}

template<bool SAFE>
__device__ __forceinline__ void conv_body(const float* __restrict__ src,
                                          const u64* __restrict__ kw2,
                                          int row0, int col0,
                                          u64 acc01[4], u64 acc23[4]) {
    #pragma unroll
    for (int r = 0; r < 10; r++) {
        const int gy = row0 + r - 3;
        const float* p = src + (size_t)(SAFE ? gy : (gy & 1023)) * 1024 + col0;

        float4 A0, A1, A2;
        if (SAFE) {
            A0 = *(const float4*)(p);
            A1 = *(const float4*)(p + 4);
            A2 = *(const float4*)(p + 8);
        } else {
            const float4 Z = make_float4(0.f, 0.f, 0.f, 0.f);
            const bool yok  = (unsigned)gy < 1024u;
            const bool xok0 = (unsigned)(col0)     < 1024u;
            const bool xok2 = (unsigned)(col0 + 8) < 1024u;
            A0 = (yok && xok0) ? *(const float4*)(p)     : Z;
            A1 =  yok          ? *(const float4*)(p + 4) : Z;
            A2 = (yok && xok2) ? *(const float4*)(p + 8) : Z;
        }

        float v[12] = {A0.x, A0.y, A0.z, A0.w, A1.x, A1.y, A1.z, A1.w,
                       A2.x, A2.y, A2.z, A2.w};
        u64 P[9];
        #pragma unroll
        for (int i = 0; i < 9; i++) P[i] = pk2(v[i + 1], v[i + 2]);

        #pragma unroll
        for (int o = 0; o < 4; o++) {
            const int ky = r - o;
            if (ky >= 0 && ky < KS) {
                #pragma unroll
                for (int kx = 0; kx < KS; kx++) {
                    u64 ww = kw2[ky * 7 + kx];   // LDS.64 broadcast, feeds 2 fma2
                    fma2(acc01[o], P[kx],     ww);
                    fma2(acc23[o], P[kx + 2], ww);
                }
            }
        }
    }
}

__global__ __launch_bounds__(512, 2)
void Conv_8443905704574_kernel(const float* __restrict__ img,
                               const float* __restrict__ ker,
                               float* __restrict__ out) {
    __shared__ u64 kw2[49];

    const int tid = threadIdx.x;
    if (tid < 49) {
        float w = ker[tid];
        kw2[tid] = pk2(w, w);
    }
    __syncthreads();             // only barrier in the kernel

    const int tx   = tid & 31;   // 4 contiguous output px per thread
    const int ty   = tid >> 5;   // 0..15
    const int bx   = blockIdx.x * TILE_W;
    const int by   = blockIdx.y * TILE_H;
    const int b    = blockIdx.z;
    const int row0 = by + ty * 4;           // first output row (global)
    const int col0 = bx + tx * 4 - 4;       // aligned read base, multiple of 4

    // reference convolves only the LAST channel and broadcasts it
    const float* __restrict__ src = img + ((size_t)b * 3 + 2) * (size_t)(1024 * 1024);

    u64 acc01[4], acc23[4];
    #pragma unroll
    for (int o = 0; o < 4; o++) { acc01[o] = 0ull; acc23[o] = 0ull; }

    // CTA-uniform interior test: no thread of this CTA can touch a border.
    // x: col0 in [bx-4, bx+124+8+3]; safe iff bx!=0 && bx!=896.
    // y: gy in [by-3, by+66];       safe iff by!=0 && by!=960.
    const bool interior = (bx != 0) & (bx != 1024 - TILE_W)
                        & (by != 0) & (by != 1024 - TILE_H);

    if (interior)
        conv_body<true>(src, kw2, row0, col0, acc01, acc23);
    else
        conv_body<false>(src, kw2, row0, col0, acc01, acc23);

    const int ox = bx + tx * 4;
    size_t obase = (size_t)b * 3 * 1024 * 1024;
    #pragma unroll
    for (int o = 0; o < 4; o++) {
        float4 r4;
        unpk2(acc01[o], r4.x, r4.y);
        unpk2(acc23[o], r4.z, r4.w);
        size_t off = obase + (size_t)(row0 + o) * 1024 + ox;
        #pragma unroll
        for (int c = 0; c < 3; c++)
            __stcs((float4*)(out + off + (size_t)c * 1024 * 1024), r4);
    }
}

extern "C" void kernel_launch(void* const* d_in, const int* in_sizes, int n_in,
                              void* d_out, int out_size) {
    const float* img = (const float*)d_in[0];
    const float* ker = (const float*)d_in[1];
    float* out = (float*)d_out;

    dim3 grid(1024 / TILE_W, 1024 / TILE_H, 16);   // 8 x 16 x 16 = 2048 CTAs
    Conv_8443905704574_kernel<<<grid, 512>>>(img, ker, out);
}

// round 12
// speedup vs baseline: 1.3320x; 1.3320x over previous
#include <cuda_runtime.h>

#define KS 7
#define TILE_W 128
#define TILE_H 64

typedef unsigned long long u64;

// static zero page for out-of-bounds halo reads (zero-initialized, never written)
__device__ __align__(16) float zpad[16];

__device__ __forceinline__ u64 pk2(float lo, float hi) {
    u64 r; asm("mov.b64 %0, {%1,%2};" : "=l"(r) : "f"(lo), "f"(hi)); return r;
}
__device__ __forceinline__ void fma2(u64& d, u64 a, u64 b) {
    asm("fma.rn.f32x2 %0, %1, %2, %0;" : "+l"(d) : "l"(a), "l"(b));
}
__device__ __forceinline__ void unpk2(u64 v, float& lo, float& hi) {
    asm("mov.b64 {%0,%1}, %2;" : "=f"(lo), "=f"(hi) : "l"(v));
}

__global__ __launch_bounds__(512, 2)
void Conv_8443905704574_kernel(const float* __restrict__ img,
                               const float* __restrict__ ker,
                               float* __restrict__ out) {
    __shared__ u64 kw2[49];

    const int tid = threadIdx.x;
    if (tid < 49) {
        float w = ker[tid];
        kw2[tid] = pk2(w, w);
    }
    __syncthreads();             // only barrier in the kernel

    const int tx   = tid & 31;   // 4 contiguous output px per thread
    const int ty   = tid >> 5;   // 0..15
    const int bx   = blockIdx.x * TILE_W;
    const int by   = blockIdx.y * TILE_H;
    const int b    = blockIdx.z;
    const int row0 = by + ty * 4;           // first output row (global)
    const int col0 = bx + tx * 4 - 4;       // aligned read base, multiple of 4

    // reference convolves only the LAST channel and broadcasts it
    const float* __restrict__ src = img + ((size_t)b * 3 + 2) * (size_t)(1024 * 1024);
    const float* zb = zpad;

    u64 acc01[4], acc23[4];
    #pragma unroll
    for (int o = 0; o < 4; o++) { acc01[o] = 0ull; acc23[o] = 0ull; }

    // x-edge predicates: loop-invariant, hoisted
    const bool xok0 = (unsigned)(col0)     < 1024u;  // false only at left image edge
    const bool xok2 = (unsigned)(col0 + 8) < 1024u;  // false only at right image edge
    // middle chunk cols col0+4 .. col0+7 always inside [0,1024)

    // sliding 10-row window; each input row read once, feeds up to 4 output rows
    #pragma unroll
    for (int r = 0; r < 10; r++) {
        const int gy = row0 + r - 3;
        const float* rp = src + (size_t)gy * 1024 + col0;   // wild if gy OOB; unused then

        // address-select instead of data-select: OOB -> zero page
        const float* base = ((unsigned)gy < 1024u) ? rp   : zb;
        const float* p0   = xok0                   ? base : zb;
        const float* p2   = xok2                   ? base : zb;

        float4 A0 = *(const float4*)(p0);
        float4 A1 = *(const float4*)(base + (base == zb ? 0 : 4));
        float4 A2 = *(const float4*)(p2 + (p2 == zb ? 0 : 8));

        float v[12] = {A0.x, A0.y, A0.z, A0.w, A1.x, A1.y, A1.z, A1.w,
                       A2.x, A2.y, A2.z, A2.w};
        u64 P[9];
        #pragma unroll
        for (int i = 0; i < 9; i++) P[i] = pk2(v[i + 1], v[i + 2]);

        #pragma unroll
        for (int o = 0; o < 4; o++) {
            const int ky = r - o;
            if (ky >= 0 && ky < KS) {
                #pragma unroll
                for (int kx = 0; kx < KS; kx++) {
                    u64 ww = kw2[ky * 7 + kx];   // LDS.64 broadcast, feeds 2 fma2
                    fma2(acc01[o], P[kx],     ww);
                    fma2(acc23[o], P[kx + 2], ww);
                }
            }
        }
    }

    const int ox = bx + tx * 4;
    size_t obase = (size_t)b * 3 * 1024 * 1024;
    #pragma unroll
    for (int o = 0; o < 4; o++) {
        float4 r4;
        unpk2(acc01[o], r4.x, r4.y);
        unpk2(acc23[o], r4.z, r4.w);
        size_t off = obase + (size_t)(row0 + o) * 1024 + ox;
        #pragma unroll
        for (int c = 0; c < 3; c++)
            __stcs((float4*)(out + off + (size_t)c * 1024 * 1024), r4);
    }
}

extern "C" void kernel_launch(void* const* d_in, const int* in_sizes, int n_in,
                              void* d_out, int out_size) {
    const float* img = (const float*)d_in[0];
    const float* ker = (const float*)d_in[1];
    float* out = (float*)d_out;

    dim3 grid(1024 / TILE_W, 1024 / TILE_H, 16);   // 8 x 16 x 16 = 2048 CTAs
    Conv_8443905704574_kernel<<<grid, 512>>>(img, ker, out);
}